// round 15
// baseline (speedup 1.0000x reference)
#include <cuda_runtime.h>
#include <math.h>
#include <stdint.h>

#define BB 2
#define SS 512
#define DD 768
#define HH 12
#define NLAYER 6
#define VV 32000
#define HDIM 64
#define DFF 3072
#define EPSF 1e-6f

// ---------------- scratch (device globals; no allocs allowed) ----------------
__device__ float g_h  [BB*SS*DD];
__device__ float g_hn [BB*SS*DD];
__device__ float g_q  [BB*SS*DD];
__device__ float g_k  [BB*SS*DD];
__device__ float g_v  [BB*SS*DD];
__device__ float g_ctx[BB*SS*DD];
__device__ float g_ffn[BB*SS*DFF];
__device__ float g_sc [BB*HH*SS*SS];
__device__ float g_part[4*BB*SS*DD];
// tf32-rounded weights (ORIGINAL [K,N] layouts)
__device__ float g_wqR[NLAYER*DD*DD];
__device__ float g_wkR[NLAYER*DD*DD];
__device__ float g_wvR[NLAYER*DD*DD];
__device__ float g_woR[NLAYER*DD*DD];
__device__ float g_w1R[NLAYER*DD*DFF];
__device__ float g_w2R[NLAYER*DFF*DD];
__device__ float g_hwR[(long long)VV*DD];

__device__ __forceinline__ uint32_t f2tf32(float x) {
    uint32_t r;
    asm("cvt.rna.tf32.f32 %0, %1;" : "=r"(r) : "f"(x));
    return r;
}
__device__ __forceinline__ float rndtf32(float x) { return __uint_as_float(f2tf32(x)); }

__device__ __forceinline__ float gelu_f(float v) {
    float t = v + 0.044715f * v * v * v;
    return 0.5f * v * (1.0f + tanhf(0.7978845608028654f * t));
}
__device__ __forceinline__ uint32_t smem_u32(const void* p) {
    uint32_t a;
    asm("{ .reg .u64 t; cvta.to.shared.u64 t, %1; cvt.u32.u64 %0, t; }" : "=r"(a) : "l"(p));
    return a;
}
#define CP_ASYNC16(dst, src) \
    asm volatile("cp.async.cg.shared.global [%0], [%1], 16;" :: "r"(dst), "l"(src))
#define CP_COMMIT() asm volatile("cp.async.commit_group;" ::: "memory")
#define CP_WAIT0() asm volatile("cp.async.wait_group 0;" ::: "memory")

// ---------------- embedding ----------------
__global__ void embed_kernel(const int* __restrict__ x, const float* __restrict__ tok,
                             const float* __restrict__ pos, float* __restrict__ out) {
    int idx = blockIdx.x * blockDim.x + threadIdx.x;
    if (idx >= BB*SS*DD) return;
    int d  = idx % DD;
    int bs = idx / DD;
    int s  = bs % SS;
    out[idx] = tok[(long long)x[bs]*DD + d] + pos[s*DD + d];
}

// ---------------- fused tf32 round of ALL weights (one launch) ----------------
__global__ void round_all_kernel(const float* __restrict__ wq, float* __restrict__ wqR,
                                 const float* __restrict__ wk, float* __restrict__ wkR,
                                 const float* __restrict__ wv, float* __restrict__ wvR,
                                 const float* __restrict__ wo, float* __restrict__ woR,
                                 const float* __restrict__ w1, float* __restrict__ w1R,
                                 const float* __restrict__ w2, float* __restrict__ w2R,
                                 const float* __restrict__ hw, float* __restrict__ hwR)
{
    const long long sDD = (long long)NLAYER*DD*DD/4;
    const long long sFF = (long long)NLAYER*DD*DFF/4;
    const long long sHW = (long long)VV*DD/4;
    long long i = (long long)blockIdx.x * blockDim.x + threadIdx.x;
    const float* in; float* out; long long off;
    if      (i <   sDD)           { in = wq; out = wqR; off = i; }
    else if (i < 2*sDD)           { in = wk; out = wkR; off = i -   sDD; }
    else if (i < 3*sDD)           { in = wv; out = wvR; off = i - 2*sDD; }
    else if (i < 4*sDD)           { in = wo; out = woR; off = i - 3*sDD; }
    else if (i < 4*sDD +   sFF)   { in = w1; out = w1R; off = i - 4*sDD; }
    else if (i < 4*sDD + 2*sFF)   { in = w2; out = w2R; off = i - 4*sDD - sFF; }
    else if (i < 4*sDD + 2*sFF + sHW) { in = hw; out = hwR; off = i - 4*sDD - 2*sFF; }
    else return;
    float4 v = ((const float4*)in)[off];
    v.x = rndtf32(v.x); v.y = rndtf32(v.y); v.z = rndtf32(v.z); v.w = rndtf32(v.w);
    ((float4*)out)[off] = v;
}

// ---------------- "DummyNorm" (standalone; first layer only) ----------------
__global__ void norm_kernel(const float* __restrict__ x, const float* __restrict__ sc,
                            const float* __restrict__ bi, float* __restrict__ y) {
    int row = blockIdx.x;
    const float* xr = x + (long long)row * DD;
    float* yr = y + (long long)row * DD;
    int tid = threadIdx.x;
    float sum = 0.f, sq = 0.f;
    for (int i = tid; i < DD; i += 256) { float v = xr[i]; sum += v; sq += v*v; }
    __shared__ float s1[256], s2[256];
    s1[tid] = sum; s2[tid] = sq; __syncthreads();
    for (int st = 128; st > 0; st >>= 1) {
        if (tid < st) { s1[tid] += s1[tid+st]; s2[tid] += s2[tid+st]; }
        __syncthreads();
    }
    float mean = s1[0] / (float)DD;
    float var  = (s2[0] - (float)DD * mean * mean) / (float)(DD - 1);
    float inv  = 1.f / (sqrtf(fmaxf(var, 0.f)) + EPSF);
    for (int i = tid; i < DD; i += 256)
        yr[i] = rndtf32(sc[i] * (xr[i] - mean) * inv + bi[i]);
}

// ---------------- fused split-K reduce + residual + DummyNorm ----------------
__global__ void reduce_norm_kernel(const float* __restrict__ part, const float* __restrict__ bias,
                                   const float* __restrict__ res, float* __restrict__ hout,
                                   const float* __restrict__ ns, const float* __restrict__ nb,
                                   float* __restrict__ hn, int MN) {
    int row = blockIdx.x;
    int tid = threadIdx.x;
    __shared__ float s1[256], s2[256];
    __shared__ float vrow[DD];
    float sum = 0.f, sq = 0.f;
    for (int i = tid; i < DD; i += 256) {
        int idx = row * DD + i;
        float v = part[idx] + part[idx + MN] + part[idx + 2*MN] + part[idx + 3*MN]
                + bias[i] + res[idx];
        vrow[i] = v; sum += v; sq += v*v;
    }
    s1[tid] = sum; s2[tid] = sq; __syncthreads();
    for (int st = 128; st > 0; st >>= 1) {
        if (tid < st) { s1[tid] += s1[tid+st]; s2[tid] += s2[tid+st]; }
        __syncthreads();
    }
    float mean = s1[0] / (float)DD;
    float var  = (s2[0] - (float)DD * mean * mean) / (float)(DD - 1);
    float inv  = 1.f / (sqrtf(fmaxf(var, 0.f)) + EPSF);
    for (int i = tid; i < DD; i += 256) {
        float v = vrow[i];
        int idx = row * DD + i;
        hout[idx] = v;
        hn[idx] = rndtf32(ns[i] * (v - mean) * inv + nb[i]);
    }
}

// ---------------- masked+scaled softmax; output tf32-rounded ----------------
__global__ void softmax_kernel(float* __restrict__ scores) {
    int row = blockIdx.x;
    int q = row % SS;
    float* p = scores + (long long)row * SS;
    int tid = threadIdx.x;
    const float scale = 0.125f;
    float m = -1e30f;
    for (int k = q + tid; k < SS; k += 128) m = fmaxf(m, p[k] * scale);
    __shared__ float sh[128];
    sh[tid] = m; __syncthreads();
    for (int st = 64; st > 0; st >>= 1) { if (tid < st) sh[tid] = fmaxf(sh[tid], sh[tid+st]); __syncthreads(); }
    m = sh[0]; __syncthreads();
    float sum = 0.f;
    for (int k = q + tid; k < SS; k += 128) { float e = __expf(p[k]*scale - m); p[k] = e; sum += e; }
    sh[tid] = sum; __syncthreads();
    for (int st = 64; st > 0; st >>= 1) { if (tid < st) sh[tid] += sh[tid+st]; __syncthreads(); }
    float inv = 1.f / sh[0];
    for (int k = q + tid; k < SS; k += 128) p[k] = rndtf32(p[k] * inv);
    for (int k = tid; k < q; k += 128) p[k] = 0.f;
}

// ---------------- tf32 mma.sync GEMM (single-barrier + fragment ping-pong) ----------------
// Template: TRANSB, NT (64/128/256). 128-row M tile, warp tile 64x64. blockDim = NT.
// attnMode: 0 normal | 1 QK skip fully-masked tiles | 2 PV K-loop starts at m0
#define AROW 36
#define SA_W (128*AROW)

template<int TRANSB, int NT>
__global__ void __launch_bounds__(NT)
mma_gemm(const float* __restrict__ A,
         const float* B0, const float* B1, const float* B2,
         float* C0, float* C1, float* C2,
         const float* __restrict__ bias, const float* __restrict__ res,
         int K, int lda, int ldb, int ldc, int act, int nsel,
         long long splitStride, int rndOut, int zdiv, int attnMode,
         long long saz1, long long saz2, long long sbz1, long long sbz2,
         long long scz1, long long scz2)
{
    constexpr int BROW = TRANSB ? AROW : (NT + 8);
    constexpr int SB_W = TRANSB ? (NT * AROW) : (32 * BROW);
    constexpr int NWN = NT / 64;

    extern __shared__ uint32_t smem[];
    uint32_t* SA[2] = { smem,          smem + SA_W };
    uint32_t* SB[2] = { smem + 2*SA_W, smem + 2*SA_W + SB_W };

    int tid  = threadIdx.x;
    int wid  = tid >> 5;
    int lane = tid & 31;
    int warp_m = wid / NWN;
    int warp_n = wid % NWN;
    int grp = lane >> 2, qid = lane & 3;

    long long m0 = (long long)blockIdx.y * 128;
    long long n0 = (long long)blockIdx.x * NT;

    if (attnMode == 1 && n0 + NT <= m0) return;   // fully-masked QK tile

    int z = blockIdx.z;
    const float* Ap = A;
    const float* Bp = B0;
    float*       Cp = C0;
    if (nsel == 3) {
        Bp = (z == 0) ? B0 : ((z == 1) ? B1 : B2);
        Cp = (z == 0) ? C0 : ((z == 1) ? C1 : C2);
    } else if (splitStride > 0) {
        Ap = A  + (long long)z * K;
        Bp = B0 + (long long)z * K * ldb;
        Cp = C0 + (long long)z * splitStride;
    } else if (zdiv > 0) {
        int zd = z / zdiv, zm = z % zdiv;
        Ap = A  + zd*saz1 + zm*saz2;
        Bp = B0 + zd*sbz1 + zm*sbz2;
        Cp = C0 + zd*scz1 + zm*scz2;
    }

    // A staging: 128 rows x 32 k = 1024 f4
    int a_r = tid >> 3;
    int a_c = (tid & 7) * 4;
    constexpr int A_ST = NT / 8;
    constexpr int A_IT = 128 / A_ST;
    // B staging
    constexpr int TPBR = NT / 8;
    int b_r0 = TRANSB ? (tid >> 3) : (tid / TPBR);
    int b_c0 = TRANSB ? ((tid & 7) * 4) : ((tid % TPBR) * 8);

    float acc[32][4];
    #pragma unroll
    for (int t = 0; t < 32; t++)
        #pragma unroll
        for (int u = 0; u < 4; u++) acc[t][u] = 0.f;

    int NC = K >> 5;
    int c0 = (attnMode == 2) ? (int)(m0 >> 5) : 0;
    int NCe = NC - c0;

    auto stage = [&](int bufi, int kt) {
        #pragma unroll
        for (int i = 0; i < A_IT; i++) {
            int r = a_r + i * A_ST;
            CP_ASYNC16(smem_u32(SA[bufi] + r*AROW + a_c), Ap + (m0 + r) * lda + kt + a_c);
        }
        if (TRANSB) {
            #pragma unroll
            for (int i = 0; i < A_IT; i++) {
                int r = b_r0 + i * A_ST;
                CP_ASYNC16(smem_u32(SB[bufi] + r*AROW + b_c0), Bp + (n0 + r) * ldb + kt + b_c0);
            }
        } else {
            #pragma unroll
            for (int i = 0; i < 4; i++) {
                int r = b_r0 + i * 8;
                const float* src = Bp + (long long)(kt + r) * ldb + n0 + b_c0;
                CP_ASYNC16(smem_u32(SB[bufi] + r*BROW + b_c0),     src);
                CP_ASYNC16(smem_u32(SB[bufi] + r*BROW + b_c0 + 4), src + 4);
            }
        }
        CP_COMMIT();
    };

    stage(0, c0 * 32);

    for (int cc = 0; cc < NCe; cc++) {
        int buf = cc & 1;
        CP_WAIT0();
        __syncthreads();
        if (cc + 1 < NCe) stage(buf ^ 1, (c0 + cc + 1) * 32);

        const uint32_t* As_ = SA[buf];
        const uint32_t* Bs_ = SB[buf];

        // fragment loaders (register ping-pong across ks-steps)
        auto ldfrag = [&](uint32_t af[4][4], uint32_t bf[8][2], int ks) {
            #pragma unroll
            for (int i = 0; i < 4; i++) {
                int mr = warp_m*64 + i*16 + grp;
                af[i][0] = As_[(mr    )*AROW + ks + qid];
                af[i][1] = As_[(mr + 8)*AROW + ks + qid];
                af[i][2] = As_[(mr    )*AROW + ks + qid + 4];
                af[i][3] = As_[(mr + 8)*AROW + ks + qid + 4];
            }
            #pragma unroll
            for (int j = 0; j < 8; j++) {
                int nr = warp_n*64 + j*8 + grp;
                if (TRANSB) {
                    bf[j][0] = Bs_[nr*AROW + ks + qid];
                    bf[j][1] = Bs_[nr*AROW + ks + qid + 4];
                } else {
                    bf[j][0] = Bs_[(ks + qid    )*BROW + nr];
                    bf[j][1] = Bs_[(ks + qid + 4)*BROW + nr];
                }
            }
        };
        auto domma = [&](uint32_t af[4][4], uint32_t bf[8][2]) {
            #pragma unroll
            for (int i = 0; i < 4; i++)
                #pragma unroll
                for (int j = 0; j < 8; j++) {
                    int t = i*8 + j;
                    asm volatile(
                        "mma.sync.aligned.m16n8k8.row.col.f32.tf32.tf32.f32 "
                        "{%0,%1,%2,%3}, {%4,%5,%6,%7}, {%8,%9}, {%0,%1,%2,%3};"
                        : "+f"(acc[t][0]), "+f"(acc[t][1]), "+f"(acc[t][2]), "+f"(acc[t][3])
                        : "r"(af[i][0]), "r"(af[i][1]), "r"(af[i][2]), "r"(af[i][3]),
                          "r"(bf[j][0]), "r"(bf[j][1]));
                }
        };

        uint32_t afA[4][4], bfA[8][2], afB[4][4], bfB[8][2];
        ldfrag(afA, bfA, 0);
        ldfrag(afB, bfB, 8);          // in flight while computing ks=0
        domma(afA, bfA);
        ldfrag(afA, bfA, 16);         // in flight while computing ks=8
        domma(afB, bfB);
        ldfrag(afB, bfB, 24);         // in flight while computing ks=16
        domma(afA, bfA);
        domma(afB, bfB);
    }

    // ---- epilogue ----
    bool raw = (splitStride > 0);
    #pragma unroll
    for (int i = 0; i < 4; i++) {
        #pragma unroll
        for (int j = 0; j < 8; j++) {
            int t = i*8 + j;
            long long m = m0 + warp_m*64 + i*16 + grp;
            long long n = n0 + warp_n*64 + j*8 + qid*2;
            float bx = 0.f, by = 0.f;
            if (!raw && bias) { bx = bias[n]; by = bias[n+1]; }
            #pragma unroll
            for (int half = 0; half < 2; half++) {
                long long mm = m + half*8;
                float v0 = acc[t][half*2 + 0] + bx;
                float v1 = acc[t][half*2 + 1] + by;
                if (!raw) {
                    if (act == 1) { v0 = gelu_f(v0); v1 = gelu_f(v1); }
                    if (res) {
                        float2 r2 = *(const float2*)(res + mm*ldc + n);
                        v0 += r2.x; v1 += r2.y;
                    }
                    if (rndOut) { v0 = rndtf32(v0); v1 = rndtf32(v1); }
                }
                float2 o; o.x = v0; o.y = v1;
                *(float2*)(Cp + mm*ldc + n) = o;
            }
        }
    }
}

#define SMEM_T0_64  ((2*SA_W + 2*32*72)*4)
#define SMEM_T0_128 ((2*SA_W + 2*32*136)*4)
#define SMEM_T1_128 ((2*SA_W + 2*128*AROW)*4)
#define SMEM_T0_256 ((2*SA_W + 2*32*264)*4)

// ---- launch helpers ----
static void launch_mma(const float* A, const float* B0, const float* B1, const float* B2,
                       float* C0, float* C1, float* C2,
                       const float* bias, const float* res,
                       int M, int N, int K, int ldb, int ldc, int act, int nsel, int rndOut)
{
    dim3 grid(N/128, M/128, nsel), blk(128);
    mma_gemm<0,128><<<grid, blk, SMEM_T0_128>>>(A, B0, B1, B2, C0, C1, C2, bias, res,
        K, K, ldb, ldc, act, nsel, 0, rndOut, 0, 0, 0,0,0,0,0,0);
}

static void launch_mma_wide(const float* A, const float* B, float* C,
                            const float* bias, int M, int N, int K, int ldb, int ldc)
{
    dim3 grid(N/256, M/128, 1), blk(256);
    mma_gemm<0,256><<<grid, blk, SMEM_T0_256>>>(A, B, B, B, C, C, C, bias, 0,
        K, K, ldb, ldc, 0, 1, 0, 0, 0, 0, 0,0,0,0,0,0);
}

static void launch_mma_split4(const float* A, const float* B, float* part,
                              int M, int N, int K)
{
    int Ks = K / 4;
    dim3 grid(N/128, M/128, 4), blk(128);
    mma_gemm<0,128><<<grid, blk, SMEM_T0_128>>>(A, B, B, B, part, part, part, 0, 0,
        Ks, K, N, N, 0, 1, (long long)M*N, 0, 0, 0, 0,0,0,0,0,0);
}

static void launch_qk(const float* Q, const float* Kp, float* scores)
{
    const long long SD = (long long)SS * DD;
    const long long SSs = (long long)SS * SS;
    dim3 grid(SS/128, SS/128, BB*HH), blk(128);
    mma_gemm<1,128><<<grid, blk, SMEM_T1_128>>>(Q, Kp, Kp, Kp, scores, scores, scores, 0, 0,
        HDIM, DD, DD, SS, 0, 1, 0, 0, HH, 1,
        SD, HDIM, SD, HDIM, (long long)HH*SSs, SSs);
}

static void launch_pv(const float* P, const float* V, float* ctx)
{
    const long long SD = (long long)SS * DD;
    const long long SSs = (long long)SS * SS;
    dim3 grid(1, SS/128, BB*HH), blk(64);
    mma_gemm<0,64><<<grid, blk, SMEM_T0_64>>>(P, V, V, V, ctx, ctx, ctx, 0, 0,
        SS, SS, DD, DD, 0, 1, 0, 1, HH, 2,
        (long long)HH*SSs, SSs, SD, HDIM, SD, HDIM);
}

extern "C" void kernel_launch(void* const* d_in, const int* in_sizes, int n_in,
                              void* d_out, int out_size)
{
    const int*   x   = (const int*)  d_in[0];
    const float* tok = (const float*)d_in[1];
    const float* pos = (const float*)d_in[2];
    const float* n1s = (const float*)d_in[3];
    const float* n1b = (const float*)d_in[4];
    const float* n2s = (const float*)d_in[5];
    const float* n2b = (const float*)d_in[6];
    const float* wq  = (const float*)d_in[7];
    const float* wk  = (const float*)d_in[8];
    const float* wv  = (const float*)d_in[9];
    const float* wo  = (const float*)d_in[10];
    const float* bo  = (const float*)d_in[11];
    const float* w1  = (const float*)d_in[12];
    const float* b1  = (const float*)d_in[13];
    const float* w2  = (const float*)d_in[14];
    const float* b2  = (const float*)d_in[15];
    const float* fs  = (const float*)d_in[16];
    const float* fb  = (const float*)d_in[17];
    const float* hw  = (const float*)d_in[18];
    const float* hb  = (const float*)d_in[19];
    float* out = (float*)d_out;

    cudaFuncSetAttribute(mma_gemm<0,64>,  cudaFuncAttributeMaxDynamicSharedMemorySize, SMEM_T0_64);
    cudaFuncSetAttribute(mma_gemm<0,128>, cudaFuncAttributeMaxDynamicSharedMemorySize, SMEM_T0_128);
    cudaFuncSetAttribute(mma_gemm<1,128>, cudaFuncAttributeMaxDynamicSharedMemorySize, SMEM_T1_128);
    cudaFuncSetAttribute(mma_gemm<0,256>, cudaFuncAttributeMaxDynamicSharedMemorySize, SMEM_T0_256);

    float *h, *hn, *gq, *gk, *gv, *ctx, *ffn, *sc, *part;
    float *wqR, *wkR, *wvR, *woR, *w1R, *w2R, *hwR;
    cudaGetSymbolAddress((void**)&h,   g_h);
    cudaGetSymbolAddress((void**)&hn,  g_hn);
    cudaGetSymbolAddress((void**)&gq,  g_q);
    cudaGetSymbolAddress((void**)&gk,  g_k);
    cudaGetSymbolAddress((void**)&gv,  g_v);
    cudaGetSymbolAddress((void**)&ctx, g_ctx);
    cudaGetSymbolAddress((void**)&ffn, g_ffn);
    cudaGetSymbolAddress((void**)&sc,  g_sc);
    cudaGetSymbolAddress((void**)&part, g_part);
    cudaGetSymbolAddress((void**)&wqR, g_wqR);
    cudaGetSymbolAddress((void**)&wkR, g_wkR);
    cudaGetSymbolAddress((void**)&wvR, g_wvR);
    cudaGetSymbolAddress((void**)&woR, g_woR);
    cudaGetSymbolAddress((void**)&w1R, g_w1R);
    cudaGetSymbolAddress((void**)&w2R, g_w2R);
    cudaGetSymbolAddress((void**)&hwR, g_hwR);

    const int M = BB * SS;
    const int MN_DD = M * DD;

    // one fused round launch for all weights
    {
        const long long sDD = (long long)NLAYER*DD*DD/4;
        const long long sFF = (long long)NLAYER*DD*DFF/4;
        const long long sHW = (long long)VV*DD/4;
        long long total = 4*sDD + 2*sFF + sHW;
        round_all_kernel<<<(unsigned)((total + 255)/256), 256>>>(
            wq, wqR, wk, wkR, wv, wvR, wo, woR, w1, w1R, w2, w2R, hw, hwR);
    }

    embed_kernel<<<(BB*SS*DD + 255)/256, 256>>>(x, tok, pos, h);
    norm_kernel<<<M, 256>>>(h, n1s, n1b, hn);

    for (int l = 0; l < NLAYER; l++) {
        // hn produced by standalone norm (l=0) or previous layer's fused reduce_norm
        launch_mma(hn, wqR + (long long)l*DD*DD, wkR + (long long)l*DD*DD, wvR + (long long)l*DD*DD,
                   gq, gk, gv, 0, 0, M, DD, DD, DD, DD, 0, 3, 1);

        // scores = Q . K^T (tensor, batched; fully-masked tiles skipped)
        launch_qk(gq, gk, sc);

        softmax_kernel<<<BB*HH*SS, 128>>>(sc);

        // ctx = P @ V (tensor, batched; zero K-chunks skipped; output rounded)
        launch_pv(sc, gv, ctx);

        // O-proj split-K x4 -> partials; fused reduce + residual + norm2 -> h, hn
        launch_mma_split4(ctx, woR + (long long)l*DD*DD, part, M, DD, DD);
        reduce_norm_kernel<<<M, 256>>>(part, bo + l*DD, h, h,
                                       n2s + l*DD, n2b + l*DD, hn, MN_DD);

        // ffn = gelu(hn @ w1 + b1) (tensor; output rounded)
        launch_mma(hn, w1R + (long long)l*DD*DFF, 0, 0, ffn, 0, 0,
                   b1 + l*DFF, 0, M, DFF, DD, DFF, DFF, 1, 1, 1);

        // FFN2 split-K x4 -> partials; fused reduce + residual + next norm -> h, hn
        launch_mma_split4(ffn, w2R + (long long)l*DFF*DD, part, M, DD, DFF);
        if (l < NLAYER - 1)
            reduce_norm_kernel<<<M, 256>>>(part, b2 + l*DD, h, h,
                                           n1s + (l+1)*DD, n1b + (l+1)*DD, hn, MN_DD);
        else
            reduce_norm_kernel<<<M, 256>>>(part, b2 + l*DD, h, h, fs, fb, hn, MN_DD);
    }

    // logits = hn @ head_w + head_b (tensor, 256-wide tile)
    launch_mma_wide(hn, hwR, out, hb, M, VV, DD, VV, VV);
}

// round 16
// speedup vs baseline: 1.0658x; 1.0658x over previous
#include <cuda_runtime.h>
#include <math.h>
#include <stdint.h>

#define BB 2
#define SS 512
#define DD 768
#define HH 12
#define NLAYER 6
#define VV 32000
#define HDIM 64
#define DFF 3072
#define EPSF 1e-6f

// ---------------- scratch (device globals; no allocs allowed) ----------------
__device__ float g_h  [BB*SS*DD];
__device__ float g_hn [BB*SS*DD];
__device__ float g_q  [BB*SS*DD];
__device__ float g_k  [BB*SS*DD];
__device__ float g_v  [BB*SS*DD];
__device__ float g_ctx[BB*SS*DD];
__device__ float g_ffn[BB*SS*DFF];
__device__ float g_sc [BB*HH*SS*SS];
__device__ float g_part[4*BB*SS*DD];
// tf32-rounded weights (ORIGINAL [K,N] layouts)
__device__ float g_wqR[NLAYER*DD*DD];
__device__ float g_wkR[NLAYER*DD*DD];
__device__ float g_wvR[NLAYER*DD*DD];
__device__ float g_woR[NLAYER*DD*DD];
__device__ float g_w1R[NLAYER*DD*DFF];
__device__ float g_w2R[NLAYER*DFF*DD];
__device__ float g_hwR[(long long)VV*DD];

__device__ __forceinline__ uint32_t f2tf32(float x) {
    uint32_t r;
    asm("cvt.rna.tf32.f32 %0, %1;" : "=r"(r) : "f"(x));
    return r;
}
__device__ __forceinline__ float rndtf32(float x) { return __uint_as_float(f2tf32(x)); }

__device__ __forceinline__ float gelu_f(float v) {
    float t = v + 0.044715f * v * v * v;
    return 0.5f * v * (1.0f + tanhf(0.7978845608028654f * t));
}
__device__ __forceinline__ uint32_t smem_u32(const void* p) {
    uint32_t a;
    asm("{ .reg .u64 t; cvta.to.shared.u64 t, %1; cvt.u32.u64 %0, t; }" : "=r"(a) : "l"(p));
    return a;
}
#define CP_ASYNC16(dst, src) \
    asm volatile("cp.async.cg.shared.global [%0], [%1], 16;" :: "r"(dst), "l"(src))
#define CP_COMMIT() asm volatile("cp.async.commit_group;" ::: "memory")
#define CP_WAIT0() asm volatile("cp.async.wait_group 0;" ::: "memory")

// ---------------- embedding ----------------
__global__ void embed_kernel(const int* __restrict__ x, const float* __restrict__ tok,
                             const float* __restrict__ pos, float* __restrict__ out) {
    int idx = blockIdx.x * blockDim.x + threadIdx.x;
    if (idx >= BB*SS*DD) return;
    int d  = idx % DD;
    int bs = idx / DD;
    int s  = bs % SS;
    out[idx] = tok[(long long)x[bs]*DD + d] + pos[s*DD + d];
}

// ---------------- fused tf32 round of ALL weights (one launch) ----------------
__global__ void round_all_kernel(const float* __restrict__ wq, float* __restrict__ wqR,
                                 const float* __restrict__ wk, float* __restrict__ wkR,
                                 const float* __restrict__ wv, float* __restrict__ wvR,
                                 const float* __restrict__ wo, float* __restrict__ woR,
                                 const float* __restrict__ w1, float* __restrict__ w1R,
                                 const float* __restrict__ w2, float* __restrict__ w2R,
                                 const float* __restrict__ hw, float* __restrict__ hwR)
{
    const long long sDD = (long long)NLAYER*DD*DD/4;
    const long long sFF = (long long)NLAYER*DD*DFF/4;
    const long long sHW = (long long)VV*DD/4;
    long long i = (long long)blockIdx.x * blockDim.x + threadIdx.x;
    const float* in; float* out; long long off;
    if      (i <   sDD)           { in = wq; out = wqR; off = i; }
    else if (i < 2*sDD)           { in = wk; out = wkR; off = i -   sDD; }
    else if (i < 3*sDD)           { in = wv; out = wvR; off = i - 2*sDD; }
    else if (i < 4*sDD)           { in = wo; out = woR; off = i - 3*sDD; }
    else if (i < 4*sDD +   sFF)   { in = w1; out = w1R; off = i - 4*sDD; }
    else if (i < 4*sDD + 2*sFF)   { in = w2; out = w2R; off = i - 4*sDD - sFF; }
    else if (i < 4*sDD + 2*sFF + sHW) { in = hw; out = hwR; off = i - 4*sDD - 2*sFF; }
    else return;
    float4 v = ((const float4*)in)[off];
    v.x = rndtf32(v.x); v.y = rndtf32(v.y); v.z = rndtf32(v.z); v.w = rndtf32(v.w);
    ((float4*)out)[off] = v;
}

// ---------------- "DummyNorm" (standalone; first layer only) ----------------
__global__ void norm_kernel(const float* __restrict__ x, const float* __restrict__ sc,
                            const float* __restrict__ bi, float* __restrict__ y) {
    int row = blockIdx.x;
    const float* xr = x + (long long)row * DD;
    float* yr = y + (long long)row * DD;
    int tid = threadIdx.x;
    float sum = 0.f, sq = 0.f;
    for (int i = tid; i < DD; i += 256) { float v = xr[i]; sum += v; sq += v*v; }
    __shared__ float s1[256], s2[256];
    s1[tid] = sum; s2[tid] = sq; __syncthreads();
    for (int st = 128; st > 0; st >>= 1) {
        if (tid < st) { s1[tid] += s1[tid+st]; s2[tid] += s2[tid+st]; }
        __syncthreads();
    }
    float mean = s1[0] / (float)DD;
    float var  = (s2[0] - (float)DD * mean * mean) / (float)(DD - 1);
    float inv  = 1.f / (sqrtf(fmaxf(var, 0.f)) + EPSF);
    for (int i = tid; i < DD; i += 256)
        yr[i] = rndtf32(sc[i] * (xr[i] - mean) * inv + bi[i]);
}

// ---------------- fused split-K reduce + residual + DummyNorm (float4) ----------------
__global__ void reduce_norm_kernel(const float* __restrict__ part, const float* __restrict__ bias,
                                   const float* __restrict__ res, float* __restrict__ hout,
                                   const float* __restrict__ ns, const float* __restrict__ nb,
                                   float* __restrict__ hn, int MN) {
    int row = blockIdx.x;
    int tid = threadIdx.x;                    // 256; f4 lanes: 0..191
    const int NF4 = DD / 4;                   // 192
    const int MN4 = MN / 4;
    __shared__ float s1[256], s2[256];
    __shared__ float4 vrow[DD/4];
    float sum = 0.f, sq = 0.f;
    float4 vv;
    if (tid < NF4) {
        long long i4 = (long long)row * NF4 + tid;
        float4 a = ((const float4*)part)[i4];
        float4 b = ((const float4*)part)[i4 + MN4];
        float4 c = ((const float4*)part)[i4 + 2*MN4];
        float4 d = ((const float4*)part)[i4 + 3*MN4];
        float4 bb = ((const float4*)bias)[tid];
        float4 rr = ((const float4*)res)[i4];
        vv.x = a.x + b.x + c.x + d.x + bb.x + rr.x;
        vv.y = a.y + b.y + c.y + d.y + bb.y + rr.y;
        vv.z = a.z + b.z + c.z + d.z + bb.z + rr.z;
        vv.w = a.w + b.w + c.w + d.w + bb.w + rr.w;
        vrow[tid] = vv;
        sum = vv.x + vv.y + vv.z + vv.w;
        sq  = vv.x*vv.x + vv.y*vv.y + vv.z*vv.z + vv.w*vv.w;
    }
    s1[tid] = sum; s2[tid] = sq; __syncthreads();
    for (int st = 128; st > 0; st >>= 1) {
        if (tid < st) { s1[tid] += s1[tid+st]; s2[tid] += s2[tid+st]; }
        __syncthreads();
    }
    float mean = s1[0] / (float)DD;
    float var  = (s2[0] - (float)DD * mean * mean) / (float)(DD - 1);
    float inv  = 1.f / (sqrtf(fmaxf(var, 0.f)) + EPSF);
    if (tid < NF4) {
        long long i4 = (long long)row * NF4 + tid;
        float4 ss = ((const float4*)ns)[tid];
        float4 bb = ((const float4*)nb)[tid];
        ((float4*)hout)[i4] = vv;
        float4 o;
        o.x = rndtf32(ss.x * (vv.x - mean) * inv + bb.x);
        o.y = rndtf32(ss.y * (vv.y - mean) * inv + bb.y);
        o.z = rndtf32(ss.z * (vv.z - mean) * inv + bb.z);
        o.w = rndtf32(ss.w * (vv.w - mean) * inv + bb.w);
        ((float4*)hn)[i4] = o;
    }
}

// ---------------- masked+scaled softmax, single-pass float4; output tf32-rounded ----------------
__global__ void softmax_kernel(float* __restrict__ scores) {
    int row = blockIdx.x;
    int q = row % SS;
    float* p = scores + (long long)row * SS;
    int tid = threadIdx.x;                    // 128 == SS/4
    const float scale = 0.125f;
    float4 v = ((const float4*)p)[tid];
    int k0 = tid * 4;
    float vv[4] = { v.x, v.y, v.z, v.w };
    float m = -1e30f;
    #pragma unroll
    for (int j = 0; j < 4; j++)
        if (k0 + j >= q) m = fmaxf(m, vv[j] * scale);
    __shared__ float sh[128];
    sh[tid] = m; __syncthreads();
    for (int st = 64; st > 0; st >>= 1) { if (tid < st) sh[tid] = fmaxf(sh[tid], sh[tid+st]); __syncthreads(); }
    m = sh[0]; __syncthreads();
    float e[4];
    float sum = 0.f;
    #pragma unroll
    for (int j = 0; j < 4; j++) {
        e[j] = (k0 + j >= q) ? __expf(vv[j] * scale - m) : 0.f;
        sum += e[j];
    }
    sh[tid] = sum; __syncthreads();
    for (int st = 64; st > 0; st >>= 1) { if (tid < st) sh[tid] += sh[tid+st]; __syncthreads(); }
    float inv = 1.f / sh[0];
    float4 o;
    o.x = rndtf32(e[0] * inv);
    o.y = rndtf32(e[1] * inv);
    o.z = rndtf32(e[2] * inv);
    o.w = rndtf32(e[3] * inv);
    ((float4*)p)[tid] = o;
}

// ---------------- tf32 mma.sync GEMM (R14: single-barrier pipeline) ----------------
// Template: TRANSB, NT (64/128/256). 128-row M tile, warp tile 64x64. blockDim = NT.
// attnMode: 0 normal | 1 QK skip fully-masked tiles | 2 PV K-loop starts at m0
#define AROW 36
#define SA_W (128*AROW)

template<int TRANSB, int NT>
__global__ void __launch_bounds__(NT)
mma_gemm(const float* __restrict__ A,
         const float* B0, const float* B1, const float* B2,
         float* C0, float* C1, float* C2,
         const float* __restrict__ bias, const float* __restrict__ res,
         int K, int lda, int ldb, int ldc, int act, int nsel,
         long long splitStride, int rndOut, int zdiv, int attnMode,
         long long saz1, long long saz2, long long sbz1, long long sbz2,
         long long scz1, long long scz2)
{
    constexpr int BROW = TRANSB ? AROW : (NT + 8);
    constexpr int SB_W = TRANSB ? (NT * AROW) : (32 * BROW);
    constexpr int NWN = NT / 64;

    extern __shared__ uint32_t smem[];
    uint32_t* SA[2] = { smem,          smem + SA_W };
    uint32_t* SB[2] = { smem + 2*SA_W, smem + 2*SA_W + SB_W };

    int tid  = threadIdx.x;
    int wid  = tid >> 5;
    int lane = tid & 31;
    int warp_m = wid / NWN;
    int warp_n = wid % NWN;
    int grp = lane >> 2, qid = lane & 3;

    long long m0 = (long long)blockIdx.y * 128;
    long long n0 = (long long)blockIdx.x * NT;

    if (attnMode == 1 && n0 + NT <= m0) return;   // fully-masked QK tile

    int z = blockIdx.z;
    const float* Ap = A;
    const float* Bp = B0;
    float*       Cp = C0;
    if (nsel == 3) {
        Bp = (z == 0) ? B0 : ((z == 1) ? B1 : B2);
        Cp = (z == 0) ? C0 : ((z == 1) ? C1 : C2);
    } else if (splitStride > 0) {
        Ap = A  + (long long)z * K;
        Bp = B0 + (long long)z * K * ldb;
        Cp = C0 + (long long)z * splitStride;
    } else if (zdiv > 0) {
        int zd = z / zdiv, zm = z % zdiv;
        Ap = A  + zd*saz1 + zm*saz2;
        Bp = B0 + zd*sbz1 + zm*sbz2;
        Cp = C0 + zd*scz1 + zm*scz2;
    }

    // A staging: 128 rows x 32 k = 1024 f4
    int a_r = tid >> 3;
    int a_c = (tid & 7) * 4;
    constexpr int A_ST = NT / 8;
    constexpr int A_IT = 128 / A_ST;
    // B staging
    constexpr int TPBR = NT / 8;
    int b_r0 = TRANSB ? (tid >> 3) : (tid / TPBR);
    int b_c0 = TRANSB ? ((tid & 7) * 4) : ((tid % TPBR) * 8);

    float acc[32][4];
    #pragma unroll
    for (int t = 0; t < 32; t++)
        #pragma unroll
        for (int u = 0; u < 4; u++) acc[t][u] = 0.f;

    int NC = K >> 5;
    int c0 = (attnMode == 2) ? (int)(m0 >> 5) : 0;
    int NCe = NC - c0;

    auto stage = [&](int bufi, int kt) {
        #pragma unroll
        for (int i = 0; i < A_IT; i++) {
            int r = a_r + i * A_ST;
            CP_ASYNC16(smem_u32(SA[bufi] + r*AROW + a_c), Ap + (m0 + r) * lda + kt + a_c);
        }
        if (TRANSB) {
            #pragma unroll
            for (int i = 0; i < A_IT; i++) {
                int r = b_r0 + i * A_ST;
                CP_ASYNC16(smem_u32(SB[bufi] + r*AROW + b_c0), Bp + (n0 + r) * ldb + kt + b_c0);
            }
        } else {
            #pragma unroll
            for (int i = 0; i < 4; i++) {
                int r = b_r0 + i * 8;
                const float* src = Bp + (long long)(kt + r) * ldb + n0 + b_c0;
                CP_ASYNC16(smem_u32(SB[bufi] + r*BROW + b_c0),     src);
                CP_ASYNC16(smem_u32(SB[bufi] + r*BROW + b_c0 + 4), src + 4);
            }
        }
        CP_COMMIT();
    };

    stage(0, c0 * 32);

    for (int cc = 0; cc < NCe; cc++) {
        int buf = cc & 1;
        CP_WAIT0();
        __syncthreads();
        if (cc + 1 < NCe) stage(buf ^ 1, (c0 + cc + 1) * 32);

        const uint32_t* As_ = SA[buf];
        const uint32_t* Bs_ = SB[buf];
        #pragma unroll
        for (int ks = 0; ks < 32; ks += 8) {
            uint32_t af[4][4], bf[8][2];
            #pragma unroll
            for (int i = 0; i < 4; i++) {
                int mr = warp_m*64 + i*16 + grp;
                af[i][0] = As_[(mr    )*AROW + ks + qid];
                af[i][1] = As_[(mr + 8)*AROW + ks + qid];
                af[i][2] = As_[(mr    )*AROW + ks + qid + 4];
                af[i][3] = As_[(mr + 8)*AROW + ks + qid + 4];
            }
            #pragma unroll
            for (int j = 0; j < 8; j++) {
                int nr = warp_n*64 + j*8 + grp;
                if (TRANSB) {
                    bf[j][0] = Bs_[nr*AROW + ks + qid];
                    bf[j][1] = Bs_[nr*AROW + ks + qid + 4];
                } else {
                    bf[j][0] = Bs_[(ks + qid    )*BROW + nr];
                    bf[j][1] = Bs_[(ks + qid + 4)*BROW + nr];
                }
            }
            #pragma unroll
            for (int i = 0; i < 4; i++)
                #pragma unroll
                for (int j = 0; j < 8; j++) {
                    int t = i*8 + j;
                    asm volatile(
                        "mma.sync.aligned.m16n8k8.row.col.f32.tf32.tf32.f32 "
                        "{%0,%1,%2,%3}, {%4,%5,%6,%7}, {%8,%9}, {%0,%1,%2,%3};"
                        : "+f"(acc[t][0]), "+f"(acc[t][1]), "+f"(acc[t][2]), "+f"(acc[t][3])
                        : "r"(af[i][0]), "r"(af[i][1]), "r"(af[i][2]), "r"(af[i][3]),
                          "r"(bf[j][0]), "r"(bf[j][1]));
                }
        }
    }

    // ---- epilogue ----
    bool raw = (splitStride > 0);
    #pragma unroll
    for (int i = 0; i < 4; i++) {
        #pragma unroll
        for (int j = 0; j < 8; j++) {
            int t = i*8 + j;
            long long m = m0 + warp_m*64 + i*16 + grp;
            long long n = n0 + warp_n*64 + j*8 + qid*2;
            float bx = 0.f, by = 0.f;
            if (!raw && bias) { bx = bias[n]; by = bias[n+1]; }
            #pragma unroll
            for (int half = 0; half < 2; half++) {
                long long mm = m + half*8;
                float v0 = acc[t][half*2 + 0] + bx;
                float v1 = acc[t][half*2 + 1] + by;
                if (!raw) {
                    if (act == 1) { v0 = gelu_f(v0); v1 = gelu_f(v1); }
                    if (res) {
                        float2 r2 = *(const float2*)(res + mm*ldc + n);
                        v0 += r2.x; v1 += r2.y;
                    }
                    if (rndOut) { v0 = rndtf32(v0); v1 = rndtf32(v1); }
                }
                float2 o; o.x = v0; o.y = v1;
                *(float2*)(Cp + mm*ldc + n) = o;
            }
        }
    }
}

#define SMEM_T0_64  ((2*SA_W + 2*32*72)*4)
#define SMEM_T0_128 ((2*SA_W + 2*32*136)*4)
#define SMEM_T1_128 ((2*SA_W + 2*128*AROW)*4)
#define SMEM_T0_256 ((2*SA_W + 2*32*264)*4)

// ---- launch helpers ----
static void launch_mma(const float* A, const float* B0, const float* B1, const float* B2,
                       float* C0, float* C1, float* C2,
                       const float* bias, const float* res,
                       int M, int N, int K, int ldb, int ldc, int act, int nsel, int rndOut)
{
    dim3 grid(N/128, M/128, nsel), blk(128);
    mma_gemm<0,128><<<grid, blk, SMEM_T0_128>>>(A, B0, B1, B2, C0, C1, C2, bias, res,
        K, K, ldb, ldc, act, nsel, 0, rndOut, 0, 0, 0,0,0,0,0,0);
}

static void launch_mma_wide(const float* A, const float* B, float* C,
                            const float* bias, int M, int N, int K, int ldb, int ldc)
{
    dim3 grid(N/256, M/128, 1), blk(256);
    mma_gemm<0,256><<<grid, blk, SMEM_T0_256>>>(A, B, B, B, C, C, C, bias, 0,
        K, K, ldb, ldc, 0, 1, 0, 0, 0, 0, 0,0,0,0,0,0);
}

static void launch_mma_split4(const float* A, const float* B, float* part,
                              int M, int N, int K)
{
    int Ks = K / 4;
    dim3 grid(N/128, M/128, 4), blk(128);
    mma_gemm<0,128><<<grid, blk, SMEM_T0_128>>>(A, B, B, B, part, part, part, 0, 0,
        Ks, K, N, N, 0, 1, (long long)M*N, 0, 0, 0, 0,0,0,0,0,0);
}

static void launch_qk(const float* Q, const float* Kp, float* scores)
{
    const long long SD = (long long)SS * DD;
    const long long SSs = (long long)SS * SS;
    dim3 grid(SS/128, SS/128, BB*HH), blk(128);
    mma_gemm<1,128><<<grid, blk, SMEM_T1_128>>>(Q, Kp, Kp, Kp, scores, scores, scores, 0, 0,
        HDIM, DD, DD, SS, 0, 1, 0, 0, HH, 1,
        SD, HDIM, SD, HDIM, (long long)HH*SSs, SSs);
}

static void launch_pv(const float* P, const float* V, float* ctx)
{
    const long long SD = (long long)SS * DD;
    const long long SSs = (long long)SS * SS;
    dim3 grid(1, SS/128, BB*HH), blk(64);
    mma_gemm<0,64><<<grid, blk, SMEM_T0_64>>>(P, V, V, V, ctx, ctx, ctx, 0, 0,
        SS, SS, DD, DD, 0, 1, 0, 1, HH, 2,
        (long long)HH*SSs, SSs, SD, HDIM, SD, HDIM);
}

extern "C" void kernel_launch(void* const* d_in, const int* in_sizes, int n_in,
                              void* d_out, int out_size)
{
    const int*   x   = (const int*)  d_in[0];
    const float* tok = (const float*)d_in[1];
    const float* pos = (const float*)d_in[2];
    const float* n1s = (const float*)d_in[3];
    const float* n1b = (const float*)d_in[4];
    const float* n2s = (const float*)d_in[5];
    const float* n2b = (const float*)d_in[6];
    const float* wq  = (const float*)d_in[7];
    const float* wk  = (const float*)d_in[8];
    const float* wv  = (const float*)d_in[9];
    const float* wo  = (const float*)d_in[10];
    const float* bo  = (const float*)d_in[11];
    const float* w1  = (const float*)d_in[12];
    const float* b1  = (const float*)d_in[13];
    const float* w2  = (const float*)d_in[14];
    const float* b2  = (const float*)d_in[15];
    const float* fs  = (const float*)d_in[16];
    const float* fb  = (const float*)d_in[17];
    const float* hw  = (const float*)d_in[18];
    const float* hb  = (const float*)d_in[19];
    float* out = (float*)d_out;

    cudaFuncSetAttribute(mma_gemm<0,64>,  cudaFuncAttributeMaxDynamicSharedMemorySize, SMEM_T0_64);
    cudaFuncSetAttribute(mma_gemm<0,128>, cudaFuncAttributeMaxDynamicSharedMemorySize, SMEM_T0_128);
    cudaFuncSetAttribute(mma_gemm<1,128>, cudaFuncAttributeMaxDynamicSharedMemorySize, SMEM_T1_128);
    cudaFuncSetAttribute(mma_gemm<0,256>, cudaFuncAttributeMaxDynamicSharedMemorySize, SMEM_T0_256);

    float *h, *hn, *gq, *gk, *gv, *ctx, *ffn, *sc, *part;
    float *wqR, *wkR, *wvR, *woR, *w1R, *w2R, *hwR;
    cudaGetSymbolAddress((void**)&h,   g_h);
    cudaGetSymbolAddress((void**)&hn,  g_hn);
    cudaGetSymbolAddress((void**)&gq,  g_q);
    cudaGetSymbolAddress((void**)&gk,  g_k);
    cudaGetSymbolAddress((void**)&gv,  g_v);
    cudaGetSymbolAddress((void**)&ctx, g_ctx);
    cudaGetSymbolAddress((void**)&ffn, g_ffn);
    cudaGetSymbolAddress((void**)&sc,  g_sc);
    cudaGetSymbolAddress((void**)&part, g_part);
    cudaGetSymbolAddress((void**)&wqR, g_wqR);
    cudaGetSymbolAddress((void**)&wkR, g_wkR);
    cudaGetSymbolAddress((void**)&wvR, g_wvR);
    cudaGetSymbolAddress((void**)&woR, g_woR);
    cudaGetSymbolAddress((void**)&w1R, g_w1R);
    cudaGetSymbolAddress((void**)&w2R, g_w2R);
    cudaGetSymbolAddress((void**)&hwR, g_hwR);

    const int M = BB * SS;
    const int MN_DD = M * DD;

    // one fused round launch for all weights
    {
        const long long sDD = (long long)NLAYER*DD*DD/4;
        const long long sFF = (long long)NLAYER*DD*DFF/4;
        const long long sHW = (long long)VV*DD/4;
        long long total = 4*sDD + 2*sFF + sHW;
        round_all_kernel<<<(unsigned)((total + 255)/256), 256>>>(
            wq, wqR, wk, wkR, wv, wvR, wo, woR, w1, w1R, w2, w2R, hw, hwR);
    }

    embed_kernel<<<(BB*SS*DD + 255)/256, 256>>>(x, tok, pos, h);
    norm_kernel<<<M, 256>>>(h, n1s, n1b, hn);

    for (int l = 0; l < NLAYER; l++) {
        // hn produced by standalone norm (l=0) or previous layer's fused reduce_norm
        launch_mma(hn, wqR + (long long)l*DD*DD, wkR + (long long)l*DD*DD, wvR + (long long)l*DD*DD,
                   gq, gk, gv, 0, 0, M, DD, DD, DD, DD, 0, 3, 1);

        // scores = Q . K^T (tensor, batched; fully-masked tiles skipped)
        launch_qk(gq, gk, sc);

        softmax_kernel<<<BB*HH*SS, 128>>>(sc);

        // ctx = P @ V (tensor, batched; zero K-chunks skipped; output rounded)
        launch_pv(sc, gv, ctx);

        // O-proj split-K x4 -> partials; fused reduce + residual + norm2 -> h, hn
        launch_mma_split4(ctx, woR + (long long)l*DD*DD, part, M, DD, DD);
        reduce_norm_kernel<<<M, 256>>>(part, bo + l*DD, h, h,
                                       n2s + l*DD, n2b + l*DD, hn, MN_DD);

        // ffn = gelu(hn @ w1 + b1) (tensor; output rounded)
        launch_mma(hn, w1R + (long long)l*DD*DFF, 0, 0, ffn, 0, 0,
                   b1 + l*DFF, 0, M, DFF, DD, DFF, DFF, 1, 1, 1);

        // FFN2 split-K x4 -> partials; fused reduce + residual + next norm -> h, hn
        launch_mma_split4(ffn, w2R + (long long)l*DFF*DD, part, M, DD, DFF);
        if (l < NLAYER - 1)
            reduce_norm_kernel<<<M, 256>>>(part, b2 + l*DD, h, h,
                                           n1s + (l+1)*DD, n1b + (l+1)*DD, hn, MN_DD);
        else
            reduce_norm_kernel<<<M, 256>>>(part, b2 + l*DD, h, h, fs, fb, hn, MN_DD);
    }

    // logits = hn @ head_w + head_b (tensor, 256-wide tile)
    launch_mma_wide(hn, hwR, out, hb, M, VV, DD, VV, VV);
}

// round 17
// speedup vs baseline: 1.0675x; 1.0016x over previous
#include <cuda_runtime.h>
#include <math.h>
#include <stdint.h>

#define BB 2
#define SS 512
#define DD 768
#define HH 12
#define NLAYER 6
#define VV 32000
#define HDIM 64
#define DFF 3072
#define EPSF 1e-6f

// ---------------- scratch (device globals; no allocs allowed) ----------------
__device__ float g_h  [BB*SS*DD];
__device__ float g_hn [BB*SS*DD];
__device__ float g_q  [BB*SS*DD];
__device__ float g_k  [BB*SS*DD];
__device__ float g_v  [BB*SS*DD];
__device__ float g_ctx[BB*SS*DD];
__device__ float g_ffn[BB*SS*DFF];
__device__ float g_sc [BB*HH*SS*SS];
__device__ float g_part[4*BB*SS*DD];
// tf32-rounded weights (ORIGINAL [K,N] layouts)
__device__ float g_wqR[NLAYER*DD*DD];
__device__ float g_wkR[NLAYER*DD*DD];
__device__ float g_wvR[NLAYER*DD*DD];
__device__ float g_woR[NLAYER*DD*DD];
__device__ float g_w1R[NLAYER*DD*DFF];
__device__ float g_w2R[NLAYER*DFF*DD];
__device__ float g_hwR[(long long)VV*DD];

__device__ __forceinline__ uint32_t f2tf32(float x) {
    uint32_t r;
    asm("cvt.rna.tf32.f32 %0, %1;" : "=r"(r) : "f"(x));
    return r;
}
__device__ __forceinline__ float rndtf32(float x) { return __uint_as_float(f2tf32(x)); }

__device__ __forceinline__ float gelu_f(float v) {
    float t = v + 0.044715f * v * v * v;
    return 0.5f * v * (1.0f + tanhf(0.7978845608028654f * t));
}
__device__ __forceinline__ uint32_t smem_u32(const void* p) {
    uint32_t a;
    asm("{ .reg .u64 t; cvta.to.shared.u64 t, %1; cvt.u32.u64 %0, t; }" : "=r"(a) : "l"(p));
    return a;
}
#define CP_ASYNC16(dst, src) \
    asm volatile("cp.async.cg.shared.global [%0], [%1], 16;" :: "r"(dst), "l"(src))
#define CP_COMMIT() asm volatile("cp.async.commit_group;" ::: "memory")
#define CP_WAIT0() asm volatile("cp.async.wait_group 0;" ::: "memory")

// ---------------- embedding ----------------
__global__ void embed_kernel(const int* __restrict__ x, const float* __restrict__ tok,
                             const float* __restrict__ pos, float* __restrict__ out) {
    int idx = blockIdx.x * blockDim.x + threadIdx.x;
    if (idx >= BB*SS*DD) return;
    int d  = idx % DD;
    int bs = idx / DD;
    int s  = bs % SS;
    out[idx] = tok[(long long)x[bs]*DD + d] + pos[s*DD + d];
}

// ---------------- fused tf32 round of ALL weights (one launch) ----------------
__global__ void round_all_kernel(const float* __restrict__ wq, float* __restrict__ wqR,
                                 const float* __restrict__ wk, float* __restrict__ wkR,
                                 const float* __restrict__ wv, float* __restrict__ wvR,
                                 const float* __restrict__ wo, float* __restrict__ woR,
                                 const float* __restrict__ w1, float* __restrict__ w1R,
                                 const float* __restrict__ w2, float* __restrict__ w2R,
                                 const float* __restrict__ hw, float* __restrict__ hwR)
{
    const long long sDD = (long long)NLAYER*DD*DD/4;
    const long long sFF = (long long)NLAYER*DD*DFF/4;
    const long long sHW = (long long)VV*DD/4;
    long long i = (long long)blockIdx.x * blockDim.x + threadIdx.x;
    const float* in; float* out; long long off;
    if      (i <   sDD)           { in = wq; out = wqR; off = i; }
    else if (i < 2*sDD)           { in = wk; out = wkR; off = i -   sDD; }
    else if (i < 3*sDD)           { in = wv; out = wvR; off = i - 2*sDD; }
    else if (i < 4*sDD)           { in = wo; out = woR; off = i - 3*sDD; }
    else if (i < 4*sDD +   sFF)   { in = w1; out = w1R; off = i - 4*sDD; }
    else if (i < 4*sDD + 2*sFF)   { in = w2; out = w2R; off = i - 4*sDD - sFF; }
    else if (i < 4*sDD + 2*sFF + sHW) { in = hw; out = hwR; off = i - 4*sDD - 2*sFF; }
    else return;
    float4 v = ((const float4*)in)[off];
    v.x = rndtf32(v.x); v.y = rndtf32(v.y); v.z = rndtf32(v.z); v.w = rndtf32(v.w);
    ((float4*)out)[off] = v;
}

// ---------------- "DummyNorm" (standalone; first layer only) ----------------
__global__ void norm_kernel(const float* __restrict__ x, const float* __restrict__ sc,
                            const float* __restrict__ bi, float* __restrict__ y) {
    int row = blockIdx.x;
    const float* xr = x + (long long)row * DD;
    float* yr = y + (long long)row * DD;
    int tid = threadIdx.x;
    float sum = 0.f, sq = 0.f;
    for (int i = tid; i < DD; i += 256) { float v = xr[i]; sum += v; sq += v*v; }
    __shared__ float s1[256], s2[256];
    s1[tid] = sum; s2[tid] = sq; __syncthreads();
    for (int st = 128; st > 0; st >>= 1) {
        if (tid < st) { s1[tid] += s1[tid+st]; s2[tid] += s2[tid+st]; }
        __syncthreads();
    }
    float mean = s1[0] / (float)DD;
    float var  = (s2[0] - (float)DD * mean * mean) / (float)(DD - 1);
    float inv  = 1.f / (sqrtf(fmaxf(var, 0.f)) + EPSF);
    for (int i = tid; i < DD; i += 256)
        yr[i] = rndtf32(sc[i] * (xr[i] - mean) * inv + bi[i]);
}

// ---------------- fused split-K reduce + residual + DummyNorm (float4) ----------------
__global__ void reduce_norm_kernel(const float* __restrict__ part, const float* __restrict__ bias,
                                   const float* __restrict__ res, float* __restrict__ hout,
                                   const float* __restrict__ ns, const float* __restrict__ nb,
                                   float* __restrict__ hn, int MN) {
    int row = blockIdx.x;
    int tid = threadIdx.x;                    // 256; f4 lanes: 0..191
    const int NF4 = DD / 4;                   // 192
    const int MN4 = MN / 4;
    __shared__ float s1[256], s2[256];
    float sum = 0.f, sq = 0.f;
    float4 vv;
    if (tid < NF4) {
        long long i4 = (long long)row * NF4 + tid;
        float4 a = ((const float4*)part)[i4];
        float4 b = ((const float4*)part)[i4 + MN4];
        float4 c = ((const float4*)part)[i4 + 2*MN4];
        float4 d = ((const float4*)part)[i4 + 3*MN4];
        float4 bb = ((const float4*)bias)[tid];
        float4 rr = ((const float4*)res)[i4];
        vv.x = a.x + b.x + c.x + d.x + bb.x + rr.x;
        vv.y = a.y + b.y + c.y + d.y + bb.y + rr.y;
        vv.z = a.z + b.z + c.z + d.z + bb.z + rr.z;
        vv.w = a.w + b.w + c.w + d.w + bb.w + rr.w;
        sum = vv.x + vv.y + vv.z + vv.w;
        sq  = vv.x*vv.x + vv.y*vv.y + vv.z*vv.z + vv.w*vv.w;
    }
    s1[tid] = sum; s2[tid] = sq; __syncthreads();
    for (int st = 128; st > 0; st >>= 1) {
        if (tid < st) { s1[tid] += s1[tid+st]; s2[tid] += s2[tid+st]; }
        __syncthreads();
    }
    float mean = s1[0] / (float)DD;
    float var  = (s2[0] - (float)DD * mean * mean) / (float)(DD - 1);
    float inv  = 1.f / (sqrtf(fmaxf(var, 0.f)) + EPSF);
    if (tid < NF4) {
        long long i4 = (long long)row * NF4 + tid;
        float4 ss = ((const float4*)ns)[tid];
        float4 bb = ((const float4*)nb)[tid];
        ((float4*)hout)[i4] = vv;
        float4 o;
        o.x = rndtf32(ss.x * (vv.x - mean) * inv + bb.x);
        o.y = rndtf32(ss.y * (vv.y - mean) * inv + bb.y);
        o.z = rndtf32(ss.z * (vv.z - mean) * inv + bb.z);
        o.w = rndtf32(ss.w * (vv.w - mean) * inv + bb.w);
        ((float4*)hn)[i4] = o;
    }
}

// ---------------- FUSED QK + masked softmax ----------------
// CTA: 64 queries x 512 keys, 8 warps (warp tile 64x64 keys each). 256 threads.
// Q,K: [B,S,D] fp32 (tf32-rounded). P out: rnd(softmax(QK^T/8)) with k<q zeroed.
#define QKS_SMEM ((2*64*36 + 2*512*36)*4)

__global__ void __launch_bounds__(256)
qk_softmax_kernel(const float* __restrict__ Q, const float* __restrict__ Kp,
                  float* __restrict__ P)
{
    extern __shared__ uint32_t smem[];
    uint32_t* SA[2] = { smem, smem + 64*36 };
    uint32_t* SB[2] = { smem + 2*64*36, smem + 2*64*36 + 512*36 };
    __shared__ float red[8][64];
    __shared__ float rowstat[64];

    int tid = threadIdx.x, wid = tid >> 5, lane = tid & 31;
    int grp = lane >> 2, qid = lane & 3;
    int m0 = blockIdx.x * 64;
    int z = blockIdx.y;
    int b = z / HH, hh = z % HH;
    const long long SD = (long long)SS * DD;
    const long long SSs = (long long)SS * SS;
    const float* Qb = Q + (long long)b*SD + hh*HDIM;
    const float* Kb = Kp + (long long)b*SD + hh*HDIM;
    float* Pb = P + (long long)b*HH*SSs + (long long)hh*SSs;

    // stage both K-chunks of Q (64x32 each) and K (512x32 each)
    {
        int r = tid >> 3, c4 = (tid & 7) * 4;
        #pragma unroll
        for (int ch = 0; ch < 2; ch++) {
            #pragma unroll
            for (int p = 0; p < 2; p++) {
                int rr = r + p*32;
                CP_ASYNC16(smem_u32(SA[ch] + rr*36 + c4), Qb + (long long)(m0+rr)*DD + ch*32 + c4);
            }
            #pragma unroll
            for (int p = 0; p < 16; p++) {
                int rr = r + p*32;
                CP_ASYNC16(smem_u32(SB[ch] + rr*36 + c4), Kb + (long long)rr*DD + ch*32 + c4);
            }
        }
        CP_COMMIT();
    }
    CP_WAIT0();
    __syncthreads();

    float acc[32][4];
    #pragma unroll
    for (int t = 0; t < 32; t++)
        #pragma unroll
        for (int u = 0; u < 4; u++) acc[t][u] = 0.f;

    bool active = (wid*64 + 64 > m0);   // any valid key column in this warp
    if (active) {
        #pragma unroll
        for (int ch = 0; ch < 2; ch++) {
            const uint32_t* As_ = SA[ch];
            const uint32_t* Bs_ = SB[ch];
            #pragma unroll
            for (int ks = 0; ks < 32; ks += 8) {
                uint32_t af[4][4], bf[8][2];
                #pragma unroll
                for (int i = 0; i < 4; i++) {
                    int mr = i*16 + grp;
                    af[i][0] = As_[(mr    )*36 + ks + qid];
                    af[i][1] = As_[(mr + 8)*36 + ks + qid];
                    af[i][2] = As_[(mr    )*36 + ks + qid + 4];
                    af[i][3] = As_[(mr + 8)*36 + ks + qid + 4];
                }
                #pragma unroll
                for (int j = 0; j < 8; j++) {
                    int nr = wid*64 + j*8 + grp;
                    bf[j][0] = Bs_[nr*36 + ks + qid];
                    bf[j][1] = Bs_[nr*36 + ks + qid + 4];
                }
                #pragma unroll
                for (int i = 0; i < 4; i++)
                    #pragma unroll
                    for (int j = 0; j < 8; j++) {
                        int t = i*8 + j;
                        asm volatile(
                            "mma.sync.aligned.m16n8k8.row.col.f32.tf32.tf32.f32 "
                            "{%0,%1,%2,%3}, {%4,%5,%6,%7}, {%8,%9}, {%0,%1,%2,%3};"
                            : "+f"(acc[t][0]), "+f"(acc[t][1]), "+f"(acc[t][2]), "+f"(acc[t][3])
                            : "r"(af[i][0]), "r"(af[i][1]), "r"(af[i][2]), "r"(af[i][3]),
                              "r"(bf[j][0]), "r"(bf[j][1]));
                    }
            }
        }
    }

    // ---- masked softmax over full key row (in registers + smem cross-warp) ----
    const float scale = 0.125f;
    // 1) row max
    float mx[4][2];
    #pragma unroll
    for (int i = 0; i < 4; i++)
        #pragma unroll
        for (int half = 0; half < 2; half++) {
            int lrow = i*16 + grp + half*8;
            float m = -1e30f;
            #pragma unroll
            for (int j = 0; j < 8; j++)
                #pragma unroll
                for (int c = 0; c < 2; c++) {
                    int n = wid*64 + j*8 + qid*2 + c;
                    if (n >= m0 + lrow) m = fmaxf(m, acc[i*8+j][half*2+c] * scale);
                }
            m = fmaxf(m, __shfl_xor_sync(0xffffffffu, m, 1));
            m = fmaxf(m, __shfl_xor_sync(0xffffffffu, m, 2));
            mx[i][half] = m;
        }
    if (qid == 0)
        #pragma unroll
        for (int i = 0; i < 4; i++)
            #pragma unroll
            for (int half = 0; half < 2; half++)
                red[wid][i*16 + grp + half*8] = mx[i][half];
    __syncthreads();
    if (tid < 64) {
        float m = red[0][tid];
        #pragma unroll
        for (int w = 1; w < 8; w++) m = fmaxf(m, red[w][tid]);
        rowstat[tid] = m;
    }
    __syncthreads();

    // 2) exp + row sum (overwrite acc with e)
    float sm[4][2];
    #pragma unroll
    for (int i = 0; i < 4; i++)
        #pragma unroll
        for (int half = 0; half < 2; half++) {
            int lrow = i*16 + grp + half*8;
            float rm = rowstat[lrow];
            float s = 0.f;
            #pragma unroll
            for (int j = 0; j < 8; j++)
                #pragma unroll
                for (int c = 0; c < 2; c++) {
                    int n = wid*64 + j*8 + qid*2 + c;
                    float e = (n >= m0 + lrow) ? __expf(acc[i*8+j][half*2+c] * scale - rm) : 0.f;
                    acc[i*8+j][half*2+c] = e;
                    s += e;
                }
            s += __shfl_xor_sync(0xffffffffu, s, 1);
            s += __shfl_xor_sync(0xffffffffu, s, 2);
            sm[i][half] = s;
        }
    if (qid == 0)
        #pragma unroll
        for (int i = 0; i < 4; i++)
            #pragma unroll
            for (int half = 0; half < 2; half++)
                red[wid][i*16 + grp + half*8] = sm[i][half];
    __syncthreads();
    if (tid < 64) {
        float s = 0.f;
        #pragma unroll
        for (int w = 0; w < 8; w++) s += red[w][tid];
        rowstat[tid] = 1.f / s;
    }
    __syncthreads();

    // 3) normalize + round + store
    #pragma unroll
    for (int i = 0; i < 4; i++)
        #pragma unroll
        for (int j = 0; j < 8; j++) {
            int t = i*8 + j;
            int n = wid*64 + j*8 + qid*2;
            #pragma unroll
            for (int half = 0; half < 2; half++) {
                int lrow = i*16 + grp + half*8;
                float inv = rowstat[lrow];
                long long mm = m0 + lrow;
                float2 o;
                o.x = rndtf32(acc[t][half*2 + 0] * inv);
                o.y = rndtf32(acc[t][half*2 + 1] * inv);
                *(float2*)(Pb + mm*SS + n) = o;
            }
        }
}

// ---------------- tf32 mma.sync GEMM (R14: single-barrier pipeline) ----------------
// Template: TRANSB, NT (64/128/256). 128-row M tile, warp tile 64x64. blockDim = NT.
// attnMode: 0 normal | 2 PV K-loop starts at m0
#define AROW 36
#define SA_W (128*AROW)

template<int TRANSB, int NT>
__global__ void __launch_bounds__(NT)
mma_gemm(const float* __restrict__ A,
         const float* B0, const float* B1, const float* B2,
         float* C0, float* C1, float* C2,
         const float* __restrict__ bias, const float* __restrict__ res,
         int K, int lda, int ldb, int ldc, int act, int nsel,
         long long splitStride, int rndOut, int zdiv, int attnMode,
         long long saz1, long long saz2, long long sbz1, long long sbz2,
         long long scz1, long long scz2)
{
    constexpr int BROW = TRANSB ? AROW : (NT + 8);
    constexpr int SB_W = TRANSB ? (NT * AROW) : (32 * BROW);
    constexpr int NWN = NT / 64;

    extern __shared__ uint32_t smem[];
    uint32_t* SA[2] = { smem,          smem + SA_W };
    uint32_t* SB[2] = { smem + 2*SA_W, smem + 2*SA_W + SB_W };

    int tid  = threadIdx.x;
    int wid  = tid >> 5;
    int lane = tid & 31;
    int warp_m = wid / NWN;
    int warp_n = wid % NWN;
    int grp = lane >> 2, qid = lane & 3;

    long long m0 = (long long)blockIdx.y * 128;
    long long n0 = (long long)blockIdx.x * NT;

    int z = blockIdx.z;
    const float* Ap = A;
    const float* Bp = B0;
    float*       Cp = C0;
    if (nsel == 3) {
        Bp = (z == 0) ? B0 : ((z == 1) ? B1 : B2);
        Cp = (z == 0) ? C0 : ((z == 1) ? C1 : C2);
    } else if (splitStride > 0) {
        Ap = A  + (long long)z * K;
        Bp = B0 + (long long)z * K * ldb;
        Cp = C0 + (long long)z * splitStride;
    } else if (zdiv > 0) {
        int zd = z / zdiv, zm = z % zdiv;
        Ap = A  + zd*saz1 + zm*saz2;
        Bp = B0 + zd*sbz1 + zm*sbz2;
        Cp = C0 + zd*scz1 + zm*scz2;
    }

    // A staging: 128 rows x 32 k = 1024 f4
    int a_r = tid >> 3;
    int a_c = (tid & 7) * 4;
    constexpr int A_ST = NT / 8;
    constexpr int A_IT = 128 / A_ST;
    // B staging
    constexpr int TPBR = NT / 8;
    int b_r0 = TRANSB ? (tid >> 3) : (tid / TPBR);
    int b_c0 = TRANSB ? ((tid & 7) * 4) : ((tid % TPBR) * 8);

    float acc[32][4];
    #pragma unroll
    for (int t = 0; t < 32; t++)
        #pragma unroll
        for (int u = 0; u < 4; u++) acc[t][u] = 0.f;

    int NC = K >> 5;
    int c0 = (attnMode == 2) ? (int)(m0 >> 5) : 0;
    int NCe = NC - c0;

    auto stage = [&](int bufi, int kt) {
        #pragma unroll
        for (int i = 0; i < A_IT; i++) {
            int r = a_r + i * A_ST;
            CP_ASYNC16(smem_u32(SA[bufi] + r*AROW + a_c), Ap + (m0 + r) * lda + kt + a_c);
        }
        if (TRANSB) {
            #pragma unroll
            for (int i = 0; i < A_IT; i++) {
                int r = b_r0 + i * A_ST;
                CP_ASYNC16(smem_u32(SB[bufi] + r*AROW + b_c0), Bp + (n0 + r) * ldb + kt + b_c0);
            }
        } else {
            #pragma unroll
            for (int i = 0; i < 4; i++) {
                int r = b_r0 + i * 8;
                const float* src = Bp + (long long)(kt + r) * ldb + n0 + b_c0;
                CP_ASYNC16(smem_u32(SB[bufi] + r*BROW + b_c0),     src);
                CP_ASYNC16(smem_u32(SB[bufi] + r*BROW + b_c0 + 4), src + 4);
            }
        }
        CP_COMMIT();
    };

    stage(0, c0 * 32);

    for (int cc = 0; cc < NCe; cc++) {
        int buf = cc & 1;
        CP_WAIT0();
        __syncthreads();
        if (cc + 1 < NCe) stage(buf ^ 1, (c0 + cc + 1) * 32);

        const uint32_t* As_ = SA[buf];
        const uint32_t* Bs_ = SB[buf];
        #pragma unroll
        for (int ks = 0; ks < 32; ks += 8) {
            uint32_t af[4][4], bf[8][2];
            #pragma unroll
            for (int i = 0; i < 4; i++) {
                int mr = warp_m*64 + i*16 + grp;
                af[i][0] = As_[(mr    )*AROW + ks + qid];
                af[i][1] = As_[(mr + 8)*AROW + ks + qid];
                af[i][2] = As_[(mr    )*AROW + ks + qid + 4];
                af[i][3] = As_[(mr + 8)*AROW + ks + qid + 4];
            }
            #pragma unroll
            for (int j = 0; j < 8; j++) {
                int nr = warp_n*64 + j*8 + grp;
                if (TRANSB) {
                    bf[j][0] = Bs_[nr*AROW + ks + qid];
                    bf[j][1] = Bs_[nr*AROW + ks + qid + 4];
                } else {
                    bf[j][0] = Bs_[(ks + qid    )*BROW + nr];
                    bf[j][1] = Bs_[(ks + qid + 4)*BROW + nr];
                }
            }
            #pragma unroll
            for (int i = 0; i < 4; i++)
                #pragma unroll
                for (int j = 0; j < 8; j++) {
                    int t = i*8 + j;
                    asm volatile(
                        "mma.sync.aligned.m16n8k8.row.col.f32.tf32.tf32.f32 "
                        "{%0,%1,%2,%3}, {%4,%5,%6,%7}, {%8,%9}, {%0,%1,%2,%3};"
                        : "+f"(acc[t][0]), "+f"(acc[t][1]), "+f"(acc[t][2]), "+f"(acc[t][3])
                        : "r"(af[i][0]), "r"(af[i][1]), "r"(af[i][2]), "r"(af[i][3]),
                          "r"(bf[j][0]), "r"(bf[j][1]));
                }
        }
    }

    // ---- epilogue ----
    bool raw = (splitStride > 0);
    #pragma unroll
    for (int i = 0; i < 4; i++) {
        #pragma unroll
        for (int j = 0; j < 8; j++) {
            int t = i*8 + j;
            long long m = m0 + warp_m*64 + i*16 + grp;
            long long n = n0 + warp_n*64 + j*8 + qid*2;
            float bx = 0.f, by = 0.f;
            if (!raw && bias) { bx = bias[n]; by = bias[n+1]; }
            #pragma unroll
            for (int half = 0; half < 2; half++) {
                long long mm = m + half*8;
                float v0 = acc[t][half*2 + 0] + bx;
                float v1 = acc[t][half*2 + 1] + by;
                if (!raw) {
                    if (act == 1) { v0 = gelu_f(v0); v1 = gelu_f(v1); }
                    if (res) {
                        float2 r2 = *(const float2*)(res + mm*ldc + n);
                        v0 += r2.x; v1 += r2.y;
                    }
                    if (rndOut) { v0 = rndtf32(v0); v1 = rndtf32(v1); }
                }
                float2 o; o.x = v0; o.y = v1;
                *(float2*)(Cp + mm*ldc + n) = o;
            }
        }
    }
}

#define SMEM_T0_64  ((2*SA_W + 2*32*72)*4)
#define SMEM_T0_128 ((2*SA_W + 2*32*136)*4)
#define SMEM_T0_256 ((2*SA_W + 2*32*264)*4)

// ---- launch helpers ----
static void launch_mma(const float* A, const float* B0, const float* B1, const float* B2,
                       float* C0, float* C1, float* C2,
                       const float* bias, const float* res,
                       int M, int N, int K, int ldb, int ldc, int act, int nsel, int rndOut)
{
    dim3 grid(N/128, M/128, nsel), blk(128);
    mma_gemm<0,128><<<grid, blk, SMEM_T0_128>>>(A, B0, B1, B2, C0, C1, C2, bias, res,
        K, K, ldb, ldc, act, nsel, 0, rndOut, 0, 0, 0,0,0,0,0,0);
}

static void launch_mma_wide(const float* A, const float* B, float* C,
                            const float* bias, int M, int N, int K, int ldb, int ldc)
{
    dim3 grid(N/256, M/128, 1), blk(256);
    mma_gemm<0,256><<<grid, blk, SMEM_T0_256>>>(A, B, B, B, C, C, C, bias, 0,
        K, K, ldb, ldc, 0, 1, 0, 0, 0, 0, 0,0,0,0,0,0);
}

static void launch_mma_split4(const float* A, const float* B, float* part,
                              int M, int N, int K)
{
    int Ks = K / 4;
    dim3 grid(N/128, M/128, 4), blk(128);
    mma_gemm<0,128><<<grid, blk, SMEM_T0_128>>>(A, B, B, B, part, part, part, 0, 0,
        Ks, K, N, N, 0, 1, (long long)M*N, 0, 0, 0, 0,0,0,0,0,0);
}

static void launch_pv(const float* P, const float* V, float* ctx)
{
    const long long SD = (long long)SS * DD;
    const long long SSs = (long long)SS * SS;
    dim3 grid(1, SS/128, BB*HH), blk(64);
    mma_gemm<0,64><<<grid, blk, SMEM_T0_64>>>(P, V, V, V, ctx, ctx, ctx, 0, 0,
        SS, SS, DD, DD, 0, 1, 0, 1, HH, 2,
        (long long)HH*SSs, SSs, SD, HDIM, SD, HDIM);
}

extern "C" void kernel_launch(void* const* d_in, const int* in_sizes, int n_in,
                              void* d_out, int out_size)
{
    const int*   x   = (const int*)  d_in[0];
    const float* tok = (const float*)d_in[1];
    const float* pos = (const float*)d_in[2];
    const float* n1s = (const float*)d_in[3];
    const float* n1b = (const float*)d_in[4];
    const float* n2s = (const float*)d_in[5];
    const float* n2b = (const float*)d_in[6];
    const float* wq  = (const float*)d_in[7];
    const float* wk  = (const float*)d_in[8];
    const float* wv  = (const float*)d_in[9];
    const float* wo  = (const float*)d_in[10];
    const float* bo  = (const float*)d_in[11];
    const float* w1  = (const float*)d_in[12];
    const float* b1  = (const float*)d_in[13];
    const float* w2  = (const float*)d_in[14];
    const float* b2  = (const float*)d_in[15];
    const float* fs  = (const float*)d_in[16];
    const float* fb  = (const float*)d_in[17];
    const float* hw  = (const float*)d_in[18];
    const float* hb  = (const float*)d_in[19];
    float* out = (float*)d_out;

    cudaFuncSetAttribute(mma_gemm<0,64>,  cudaFuncAttributeMaxDynamicSharedMemorySize, SMEM_T0_64);
    cudaFuncSetAttribute(mma_gemm<0,128>, cudaFuncAttributeMaxDynamicSharedMemorySize, SMEM_T0_128);
    cudaFuncSetAttribute(mma_gemm<0,256>, cudaFuncAttributeMaxDynamicSharedMemorySize, SMEM_T0_256);
    cudaFuncSetAttribute(qk_softmax_kernel, cudaFuncAttributeMaxDynamicSharedMemorySize, QKS_SMEM);

    float *h, *hn, *gq, *gk, *gv, *ctx, *ffn, *sc, *part;
    float *wqR, *wkR, *wvR, *woR, *w1R, *w2R, *hwR;
    cudaGetSymbolAddress((void**)&h,   g_h);
    cudaGetSymbolAddress((void**)&hn,  g_hn);
    cudaGetSymbolAddress((void**)&gq,  g_q);
    cudaGetSymbolAddress((void**)&gk,  g_k);
    cudaGetSymbolAddress((void**)&gv,  g_v);
    cudaGetSymbolAddress((void**)&ctx, g_ctx);
    cudaGetSymbolAddress((void**)&ffn, g_ffn);
    cudaGetSymbolAddress((void**)&sc,  g_sc);
    cudaGetSymbolAddress((void**)&part, g_part);
    cudaGetSymbolAddress((void**)&wqR, g_wqR);
    cudaGetSymbolAddress((void**)&wkR, g_wkR);
    cudaGetSymbolAddress((void**)&wvR, g_wvR);
    cudaGetSymbolAddress((void**)&woR, g_woR);
    cudaGetSymbolAddress((void**)&w1R, g_w1R);
    cudaGetSymbolAddress((void**)&w2R, g_w2R);
    cudaGetSymbolAddress((void**)&hwR, g_hwR);

    const int M = BB * SS;
    const int MN_DD = M * DD;

    // one fused round launch for all weights
    {
        const long long sDD = (long long)NLAYER*DD*DD/4;
        const long long sFF = (long long)NLAYER*DD*DFF/4;
        const long long sHW = (long long)VV*DD/4;
        long long total = 4*sDD + 2*sFF + sHW;
        round_all_kernel<<<(unsigned)((total + 255)/256), 256>>>(
            wq, wqR, wk, wkR, wv, wvR, wo, woR, w1, w1R, w2, w2R, hw, hwR);
    }

    embed_kernel<<<(BB*SS*DD + 255)/256, 256>>>(x, tok, pos, h);
    norm_kernel<<<M, 256>>>(h, n1s, n1b, hn);

    for (int l = 0; l < NLAYER; l++) {
        // hn produced by standalone norm (l=0) or previous layer's fused reduce_norm
        launch_mma(hn, wqR + (long long)l*DD*DD, wkR + (long long)l*DD*DD, wvR + (long long)l*DD*DD,
                   gq, gk, gv, 0, 0, M, DD, DD, DD, DD, 0, 3, 1);

        // fused scores + masked softmax -> P (tensor, batched over b*h)
        {
            dim3 grid(SS/64, BB*HH), blk(256);
            qk_softmax_kernel<<<grid, blk, QKS_SMEM>>>(gq, gk, sc);
        }

        // ctx = P @ V (tensor, batched; zero K-chunks skipped; output rounded)
        launch_pv(sc, gv, ctx);

        // O-proj split-K x4 -> partials; fused reduce + residual + norm2 -> h, hn
        launch_mma_split4(ctx, woR + (long long)l*DD*DD, part, M, DD, DD);
        reduce_norm_kernel<<<M, 256>>>(part, bo + l*DD, h, h,
                                       n2s + l*DD, n2b + l*DD, hn, MN_DD);

        // ffn = gelu(hn @ w1 + b1) (tensor; output rounded)
        launch_mma(hn, w1R + (long long)l*DD*DFF, 0, 0, ffn, 0, 0,
                   b1 + l*DFF, 0, M, DFF, DD, DFF, DFF, 1, 1, 1);

        // FFN2 split-K x4 -> partials; fused reduce + residual + next norm -> h, hn
        launch_mma_split4(ffn, w2R + (long long)l*DFF*DD, part, M, DD, DFF);
        if (l < NLAYER - 1)
            reduce_norm_kernel<<<M, 256>>>(part, b2 + l*DD, h, h,
                                           n1s + (l+1)*DD, n1b + (l+1)*DD, hn, MN_DD);
        else
            reduce_norm_kernel<<<M, 256>>>(part, b2 + l*DD, h, h, fs, fb, hn, MN_DD);
    }

    // logits = hn @ head_w + head_b (tensor, 256-wide tile)
    launch_mma_wide(hn, hwR, out, hb, M, VV, DD, VV, VV);
}